// round 16
// baseline (speedup 1.0000x reference)
#include <cuda_runtime.h>
#include <cuda_fp16.h>
#include <cstdint>

#define BATCH 4
#define CKD   64
#define CVD   512
#define NMEM  9216
#define MQ    2304
#define NT    128
#define NTILES 72
#define THREADS 512

#define SQK 72            // Qh/Kh row stride (halfs); 144B ≡ 16 mod 128 -> LDSM conflict-free
#define SPV 136           // Ph/Vh row stride (halfs); 272B ≡ 16 mod 128

// smem layout (float offsets)
#define OQH  0            // Qh  [128 m][72]  f16      4608 f  (prologue only)
#define OKH0 4608         // Kh buf0 [128 n][72] f16   4608 f
#define OKH1 9216         // Kh buf1                   4608 f
#define OPH  13824        // Ph [128 m][136] f16       8704 f
#define OVH  22528        // Vh [128 cv][136] f16      8704 f
#define ORA  31232        // row-sum partials [4][128]
#define OINV 31744
#define SM_FLOATS 31872
#define SMEM_BYTES (SM_FLOATS * 4)   // 127,488 B

#define QSCALE (0.125f * 1.4426950408889634f)   // fold 1/sqrt(64) + log2(e) into Q

// ---------------------------------------------------------------------------
__device__ __forceinline__ uint32_t s2u(const void* p) {
    uint32_t a;
    asm("{.reg .u64 t; cvta.to.shared.u64 t, %1; cvt.u32.u64 %0, t;}" : "=r"(a) : "l"(p));
    return a;
}
__device__ __forceinline__ uint32_t h2u(__half2 h) { return *(uint32_t*)&h; }
__device__ __forceinline__ float ex2f(float x) {
    float y; asm("ex2.approx.ftz.f32 %0, %1;" : "=f"(y) : "f"(x)); return y;
}
__device__ __forceinline__ void ldsm_x4(uint32_t r[4], uint32_t addr) {
    asm volatile("ldmatrix.sync.aligned.m8n8.x4.shared.b16 {%0,%1,%2,%3}, [%4];"
        : "=r"(r[0]), "=r"(r[1]), "=r"(r[2]), "=r"(r[3]) : "r"(addr));
}
__device__ __forceinline__ void mma16(float c[4], const uint32_t a[4],
                                      uint32_t b0, uint32_t b1) {
    asm volatile(
        "mma.sync.aligned.m16n8k16.row.col.f32.f16.f16.f32 "
        "{%0,%1,%2,%3}, {%4,%5,%6,%7}, {%8,%9}, {%0,%1,%2,%3};"
        : "+f"(c[0]), "+f"(c[1]), "+f"(c[2]), "+f"(c[3])
        : "r"(a[0]), "r"(a[1]), "r"(a[2]), "r"(a[3]), "r"(b0), "r"(b1));
}

// ---------------------------------------------------------------------------
__global__ __launch_bounds__(THREADS, 1)
void mr_kernel(const float* __restrict__ mk, const float* __restrict__ qk,
               const float* __restrict__ mv, float* __restrict__ out) {
    extern __shared__ float sm[];
    __half* Qh = (__half*)(sm + OQH);
    __half* Ph = (__half*)(sm + OPH);
    __half* Vh = (__half*)(sm + OVH);
    const uint32_t QhU = s2u(Qh), PhU = s2u(Ph), VhU = s2u(Vh);

    const int t = threadIdx.x, lane = t & 31, wid = t >> 5;
    const int g = lane >> 2, tig = lane & 3;
    const int wm = wid & 3, wn = wid >> 2;          // 4 x 4 warp grid
    const int b = blockIdx.z;
    const int m0 = blockIdx.x * 128, cv0 = blockIdx.y * 128;

    const float* qb = qk + (size_t)b * CKD * MQ + m0;
    const float* kb = mk + (size_t)b * CKD * NMEM;
    const float* vb = mv + ((size_t)b * CVD + cv0) * NMEM;

    const int nk = t & 127, chg = t >> 7;           // convert maps (coalesced)

    // ---- prologue: Q (scaled) and K_0, direct LDG-transpose converts ----
    {
        const float* qt = qb + nk;
#pragma unroll 4
        for (int i = 0; i < 8; i++) {
            int c0 = chg * 16 + 2 * i;
            float x0 = qt[(size_t)c0 * MQ] * QSCALE;
            float x1 = qt[(size_t)(c0 + 1) * MQ] * QSCALE;
            *(__half2*)&Qh[nk * SQK + c0] = __floats2half2_rn(x0, x1);
        }
        __half* Kh0 = (__half*)(sm + OKH0);
        const float* kt = kb + nk;
#pragma unroll 4
        for (int i = 0; i < 8; i++) {
            int c0 = chg * 16 + 2 * i;
            float x0 = kt[(size_t)c0 * NMEM];
            float x1 = kt[(size_t)(c0 + 1) * NMEM];
            *(__half2*)&Kh0[nk * SQK + c0] = __floats2half2_rn(x0, x1);
        }
    }
    __syncthreads();

    const int lrow = lane & 15, lcol = (lane >> 4) * 8;   // LDSM lane mapping

    // ---- persist Q A-fragments in registers (invariant over all tiles) ----
    uint32_t qf[4][2][4];
    {
        const uint32_t aA = QhU + 2 * ((wm * 32 + lrow) * SQK + lcol);
#pragma unroll
        for (int j = 0; j < 4; j++) {
            ldsm_x4(qf[j][0], aA + 32 * j);
            ldsm_x4(qf[j][1], aA + 32 * j + 32 * SQK);
        }
    }

    float oacc[2][4][4] = {};
    float rsum[4] = {0.f, 0.f, 0.f, 0.f};

    for (int tt = 0; tt < NTILES; tt++) {
        const int n0 = tt * NT;
        const uint32_t KhCU = s2u(sm + ((tt & 1) ? OKH1 : OKH0));
        __half* KhN = (__half*)(sm + ((tt & 1) ? OKH0 : OKH1));
        const bool hasN1 = (tt + 1 < NTILES);

        if (tt) __syncthreads(); // prev GEMM2 done: Vh/Ph free, KhC ready

        // ---- GEMM1 (qf·KhC^T) interleaved with V LDG->f16->Vh ----
        float sacc[2][4][4] = {};
        {
            const uint32_t aB = KhCU + 2 * ((wn * 32 + lrow) * SQK + lcol);
#pragma unroll
            for (int j = 0; j < 4; j++) {
                // V chunk loads (coalesced float4) — issue early
                int idx0 = t + THREADS * (2 * j), idx1 = idx0 + THREADS;
                float4 v0 = *(const float4*)&vb[(size_t)(idx0 >> 5) * NMEM + n0 + (idx0 & 31) * 4];
                float4 v1 = *(const float4*)&vb[(size_t)(idx1 >> 5) * NMEM + n0 + (idx1 & 31) * 4];

                uint32_t B0[4], B1[4];
                ldsm_x4(B0, aB + 32 * j);
                ldsm_x4(B1, aB + 32 * j + 32 * SQK);
                mma16(sacc[0][0], qf[j][0], B0[0], B0[2]);
                mma16(sacc[1][0], qf[j][1], B0[0], B0[2]);
                mma16(sacc[0][1], qf[j][0], B0[1], B0[3]);
                mma16(sacc[1][1], qf[j][1], B0[1], B0[3]);
                mma16(sacc[0][2], qf[j][0], B1[0], B1[2]);
                mma16(sacc[1][2], qf[j][1], B1[0], B1[2]);
                mma16(sacc[0][3], qf[j][0], B1[1], B1[3]);
                mma16(sacc[1][3], qf[j][1], B1[1], B1[3]);

                __half2 h00 = __floats2half2_rn(v0.x, v0.y);
                __half2 h01 = __floats2half2_rn(v0.z, v0.w);
                *(uint2*)&Vh[(idx0 >> 5) * SPV + (idx0 & 31) * 4] =
                    make_uint2(h2u(h00), h2u(h01));
                __half2 h10 = __floats2half2_rn(v1.x, v1.y);
                __half2 h11 = __floats2half2_rn(v1.z, v1.w);
                *(uint2*)&Vh[(idx1 >> 5) * SPV + (idx1 & 31) * 4] =
                    make_uint2(h2u(h10), h2u(h11));
            }
        }

        // ---- epilogue: exp2 -> Ph (f16), per-row partial sums ----
        {
            const int mb = wm * 32, nb = wn * 32;
            float ps[4] = {0.f, 0.f, 0.f, 0.f};
#pragma unroll
            for (int i = 0; i < 2; i++)
#pragma unroll
                for (int f = 0; f < 4; f++) {
                    float e0 = ex2f(sacc[i][f][0]);
                    float e1 = ex2f(sacc[i][f][1]);
                    float e2 = ex2f(sacc[i][f][2]);
                    float e3 = ex2f(sacc[i][f][3]);
                    ps[2 * i]     += e0 + e1;
                    ps[2 * i + 1] += e2 + e3;
                    int col = nb + 8 * f + 2 * tig;
                    int r = mb + 16 * i + g;
                    *(__half2*)&Ph[r * SPV + col] = __floats2half2_rn(e0, e1);
                    *(__half2*)&Ph[(r + 8) * SPV + col] = __floats2half2_rn(e2, e3);
                }
#pragma unroll
            for (int q = 0; q < 4; q++) {
                ps[q] += __shfl_xor_sync(0xffffffffu, ps[q], 1);
                ps[q] += __shfl_xor_sync(0xffffffffu, ps[q], 2);
                rsum[q] += ps[q];
            }
        }
        __syncthreads();           // Ph + Vh visible

        // ---- GEMM2 (Vh·Ph^T) interleaved with K-convert(tt+1) ----
        {
            const uint32_t aV = VhU + 2 * ((wm * 32 + lrow) * SPV + lcol);
            const uint32_t aP = PhU + 2 * ((wn * 32 + lrow) * SPV + lcol);
            const float* kt = kb + (size_t)(tt + 1) * NT + nk;

            float kx0 = 0.f, kx1 = 0.f;
            if (hasN1) {
                kx0 = kt[(size_t)(chg * 16) * NMEM];
                kx1 = kt[(size_t)(chg * 16 + 1) * NMEM];
            }
#pragma unroll
            for (int u = 0; u < 8; u++) {
                float nx0 = 0.f, nx1 = 0.f;
                if (hasN1 && u < 7) {     // issue next chunk's LDGs early
                    nx0 = kt[(size_t)(chg * 16 + 2 * u + 2) * NMEM];
                    nx1 = kt[(size_t)(chg * 16 + 2 * u + 3) * NMEM];
                }
                uint32_t A0[4], A1[4], B0[4], B1[4];
                ldsm_x4(A0, aV + 32 * u);
                ldsm_x4(A1, aV + 32 * u + 32 * SPV);
                ldsm_x4(B0, aP + 32 * u);
                ldsm_x4(B1, aP + 32 * u + 32 * SPV);
                mma16(oacc[0][0], A0, B0[0], B0[2]);
                mma16(oacc[1][0], A1, B0[0], B0[2]);
                mma16(oacc[0][1], A0, B0[1], B0[3]);
                mma16(oacc[1][1], A1, B0[1], B0[3]);
                mma16(oacc[0][2], A0, B1[0], B1[2]);
                mma16(oacc[1][2], A1, B1[0], B1[2]);
                mma16(oacc[0][3], A0, B1[1], B1[3]);
                mma16(oacc[1][3], A1, B1[1], B1[3]);

                if (hasN1) {
                    *(__half2*)&KhN[nk * SQK + chg * 16 + 2 * u] =
                        __floats2half2_rn(kx0, kx1);
                    kx0 = nx0; kx1 = nx1;
                }
            }
        }
    }

    // ---- finalize: row sums -> inv, normalize + store O^T ----
    __syncthreads();
    if (tig == 0) {
        float* rs = sm + ORA + wn * 128;
        const int mb = wm * 32;
        rs[mb + g]      = rsum[0];
        rs[mb + g + 8]  = rsum[1];
        rs[mb + g + 16] = rsum[2];
        rs[mb + g + 24] = rsum[3];
    }
    __syncthreads();
    if (t < 128)
        sm[OINV + t] = 1.0f / (sm[ORA + t] + sm[ORA + 128 + t] +
                               sm[ORA + 256 + t] + sm[ORA + 384 + t]);
    __syncthreads();

    {
        const int cb = wm * 32, mb2 = wn * 32;
#pragma unroll
        for (int i = 0; i < 2; i++)
#pragma unroll
            for (int f = 0; f < 4; f++) {
                int m_ = mb2 + 8 * f + 2 * tig;
                float iv0 = sm[OINV + m_], iv1 = sm[OINV + m_ + 1];
                int cv = cb + 16 * i + g;
                float* o0 = out + ((size_t)b * CVD + cv0 + cv) * MQ + m0 + m_;
                float* o1 = o0 + (size_t)8 * MQ;
                *(float2*)o0 = make_float2(oacc[i][f][0] * iv0, oacc[i][f][1] * iv1);
                *(float2*)o1 = make_float2(oacc[i][f][2] * iv0, oacc[i][f][3] * iv1);
            }
    }
}

// ---------------------------------------------------------------------------
extern "C" void kernel_launch(void* const* d_in, const int* in_sizes, int n_in,
                              void* d_out, int out_size) {
    const float* mk = (const float*)d_in[0];
    const float* qk = (const float*)d_in[1];
    const float* mv = (const float*)d_in[2];
    float* out = (float*)d_out;

    cudaFuncSetAttribute(mr_kernel, cudaFuncAttributeMaxDynamicSharedMemorySize,
                         SMEM_BYTES);
    dim3 grid(MQ / 128, CVD / 128, BATCH);   // 18 x 4 x 4 = 288
    mr_kernel<<<grid, THREADS, SMEM_BYTES>>>(mk, qk, mv, out);
}

// round 17
// speedup vs baseline: 1.1849x; 1.1849x over previous
#include <cuda_runtime.h>
#include <cuda_fp16.h>
#include <cstdint>

#define BATCH 4
#define CKD   64
#define CVD   512
#define NMEM  9216
#define MQ    2304
#define NT    64
#define NTILES 144
#define THREADS 512

#define SQK 72            // uniform row stride (halfs): 144B ≡ 16 mod 128 -> LDSM conflict-free

// smem layout (float offsets)
#define OQH  0            // Qh  [128 m][72]  f16      4608 f
#define OKH0 4608         // Kh buf0 [64 n][72] f16    2304 f
#define OKH1 6912         // Kh buf1                   2304 f
#define OPH  9216         // Ph [128 m][72] f16        4608 f
#define OVH  13824        // Vh [256 cv][72] f16       9216 f
#define ORA  23040        // row-sum partials [4][128]
#define OINV 23552
#define SM_FLOATS 23680
#define SMEM_BYTES (SM_FLOATS * 4)   // 94,720 B

#define QSCALE (0.125f * 1.4426950408889634f)   // fold 1/sqrt(64) + log2(e) into Q

// ---------------------------------------------------------------------------
__device__ __forceinline__ uint32_t s2u(const void* p) {
    uint32_t a;
    asm("{.reg .u64 t; cvta.to.shared.u64 t, %1; cvt.u32.u64 %0, t;}" : "=r"(a) : "l"(p));
    return a;
}
__device__ __forceinline__ uint32_t h2u(__half2 h) { return *(uint32_t*)&h; }
__device__ __forceinline__ float ex2f(float x) {
    float y; asm("ex2.approx.ftz.f32 %0, %1;" : "=f"(y) : "f"(x)); return y;
}
__device__ __forceinline__ void ldsm_x4(uint32_t r[4], uint32_t addr) {
    asm volatile("ldmatrix.sync.aligned.m8n8.x4.shared.b16 {%0,%1,%2,%3}, [%4];"
        : "=r"(r[0]), "=r"(r[1]), "=r"(r[2]), "=r"(r[3]) : "r"(addr));
}
__device__ __forceinline__ void mma16(float c[4], const uint32_t a[4],
                                      uint32_t b0, uint32_t b1) {
    asm volatile(
        "mma.sync.aligned.m16n8k16.row.col.f32.f16.f16.f32 "
        "{%0,%1,%2,%3}, {%4,%5,%6,%7}, {%8,%9}, {%0,%1,%2,%3};"
        : "+f"(c[0]), "+f"(c[1]), "+f"(c[2]), "+f"(c[3])
        : "r"(a[0]), "r"(a[1]), "r"(a[2]), "r"(a[3]), "r"(b0), "r"(b1));
}

// ---------------------------------------------------------------------------
__global__ __launch_bounds__(THREADS, 1)
void mr_kernel(const float* __restrict__ mk, const float* __restrict__ qk,
               const float* __restrict__ mv, float* __restrict__ out) {
    extern __shared__ float sm[];
    __half* Qh = (__half*)(sm + OQH);
    __half* Ph = (__half*)(sm + OPH);
    __half* Vh = (__half*)(sm + OVH);
    const uint32_t QhU = s2u(Qh), PhU = s2u(Ph), VhU = s2u(Vh);

    const int t = threadIdx.x, lane = t & 31, wid = t >> 5;
    const int g = lane >> 2, tig = lane & 3;
    const int wm = wid & 3, wn = wid >> 2;        // GEMM1 grid: 4(m) x 4(n)
    const int wc2 = wid & 7, wm2 = wid >> 3;      // GEMM2 grid: 8(cv) x 2(m)
    const int b = blockIdx.z;
    const int m0 = blockIdx.x * 128, cv0 = blockIdx.y * 256;

    const float* qb = qk + (size_t)b * CKD * MQ + m0;
    const float* kb = mk + (size_t)b * CKD * NMEM;
    const float* vb = mv + ((size_t)b * CVD + cv0) * NMEM;

    // ---- prologue: Q (scaled) and K_0, direct LDG-transpose converts ----
    {
        const int mq_ = t & 127, cq = t >> 7;     // 4 c-groups of 16
        const float* qt = qb + mq_;
#pragma unroll 4
        for (int i = 0; i < 8; i++) {
            int c0 = cq * 16 + 2 * i;
            float x0 = qt[(size_t)c0 * MQ] * QSCALE;
            float x1 = qt[(size_t)(c0 + 1) * MQ] * QSCALE;
            *(__half2*)&Qh[mq_ * SQK + c0] = __floats2half2_rn(x0, x1);
        }
        __half* Kh0 = (__half*)(sm + OKH0);
        const int nk0 = t & 63, ck0 = t >> 6;     // 8 c-groups of 8
        const float* kt = kb + nk0;
#pragma unroll
        for (int i = 0; i < 4; i++) {
            int c0 = ck0 * 8 + 2 * i;
            float x0 = kt[(size_t)c0 * NMEM];
            float x1 = kt[(size_t)(c0 + 1) * NMEM];
            *(__half2*)&Kh0[nk0 * SQK + c0] = __floats2half2_rn(x0, x1);
        }
    }
    __syncthreads();

    const int lrow = lane & 15, lcol = (lane >> 4) * 8;   // LDSM lane mapping
    const int nk = t & 63, ck = t >> 6;                   // K convert map

    float oacc[2][8][4] = {};
    float rsum[4] = {0.f, 0.f, 0.f, 0.f};

    for (int tt = 0; tt < NTILES; tt++) {
        const int n0 = tt * NT;
        const uint32_t KhCU = s2u(sm + ((tt & 1) ? OKH1 : OKH0));
        __half* KhN = (__half*)(sm + ((tt & 1) ? OKH0 : OKH1));
        const bool hasN1 = (tt + 1 < NTILES);

        if (tt) __syncthreads();  // prev GEMM2 done: Vh/Ph free, KhC ready

        // ---- GEMM1 (Qh·KhC^T, warp 32m x 16n) + V LDG->f16->Vh interleave ----
        float sacc[2][2][4] = {};
        {
            const uint32_t aA = QhU + 2 * ((wm * 32 + lrow) * SQK + lcol);
            const uint32_t aB = KhCU + 2 * ((wn * 16 + lrow) * SQK + lcol);
#pragma unroll
            for (int j = 0; j < 4; j++) {
                // V chunk loads: 256cv x 64n tile, 16 float4 per cv row
                int idx0 = t + THREADS * (2 * j), idx1 = idx0 + THREADS;
                float4 v0 = *(const float4*)&vb[(size_t)(idx0 >> 4) * NMEM + n0 + (idx0 & 15) * 4];
                float4 v1 = *(const float4*)&vb[(size_t)(idx1 >> 4) * NMEM + n0 + (idx1 & 15) * 4];

                uint32_t A0[4], A1[4], B[4];
                ldsm_x4(A0, aA + 32 * j);
                ldsm_x4(A1, aA + 32 * j + 32 * SQK);
                ldsm_x4(B, aB + 32 * j);
                mma16(sacc[0][0], A0, B[0], B[2]);
                mma16(sacc[1][0], A1, B[0], B[2]);
                mma16(sacc[0][1], A0, B[1], B[3]);
                mma16(sacc[1][1], A1, B[1], B[3]);

                __half2 h00 = __floats2half2_rn(v0.x, v0.y);
                __half2 h01 = __floats2half2_rn(v0.z, v0.w);
                *(uint2*)&Vh[(idx0 >> 4) * SQK + (idx0 & 15) * 4] =
                    make_uint2(h2u(h00), h2u(h01));
                __half2 h10 = __floats2half2_rn(v1.x, v1.y);
                __half2 h11 = __floats2half2_rn(v1.z, v1.w);
                *(uint2*)&Vh[(idx1 >> 4) * SQK + (idx1 & 15) * 4] =
                    make_uint2(h2u(h10), h2u(h11));
            }
        }

        // ---- epilogue: exp2 -> Ph (f16), per-lane row-sum partials ----
        {
            const int mb = wm * 32, nb = wn * 16;
#pragma unroll
            for (int i = 0; i < 2; i++)
#pragma unroll
                for (int f = 0; f < 2; f++) {
                    float e0 = ex2f(sacc[i][f][0]);
                    float e1 = ex2f(sacc[i][f][1]);
                    float e2 = ex2f(sacc[i][f][2]);
                    float e3 = ex2f(sacc[i][f][3]);
                    rsum[2 * i]     += e0 + e1;
                    rsum[2 * i + 1] += e2 + e3;
                    int col = nb + 8 * f + 2 * tig;
                    int r = mb + 16 * i + g;
                    *(__half2*)&Ph[r * SQK + col] = __floats2half2_rn(e0, e1);
                    *(__half2*)&Ph[(r + 8) * SQK + col] = __floats2half2_rn(e2, e3);
                }
        }
        __syncthreads();           // Ph + Vh visible

        // ---- GEMM2 (Vh·Ph^T, warp 32cv x 64m) + K-convert(tt+1) interleave ----
        {
            const uint32_t aV = VhU + 2 * ((wc2 * 32 + lrow) * SQK + lcol);
            const uint32_t aP = PhU + 2 * ((wm2 * 64 + lrow) * SQK + lcol);
            const float* kt = kb + (size_t)(tt + 1) * NT + nk;

            float kx0 = 0.f, kx1 = 0.f;
            if (hasN1) {
                kx0 = kt[(size_t)(ck * 8) * NMEM];
                kx1 = kt[(size_t)(ck * 8 + 1) * NMEM];
            }
#pragma unroll
            for (int u = 0; u < 4; u++) {
                float nx0 = 0.f, nx1 = 0.f;
                if (hasN1 && u < 3) {     // issue next chunk's LDGs early
                    nx0 = kt[(size_t)(ck * 8 + 2 * u + 2) * NMEM];
                    nx1 = kt[(size_t)(ck * 8 + 2 * u + 3) * NMEM];
                }
                uint32_t A0[4], A1[4];
                ldsm_x4(A0, aV + 32 * u);
                ldsm_x4(A1, aV + 32 * u + 32 * SQK);
#pragma unroll
                for (int bk = 0; bk < 4; bk++) {
                    uint32_t B[4];
                    ldsm_x4(B, aP + 32 * u + (32 * SQK) * bk);
                    mma16(oacc[0][2 * bk],     A0, B[0], B[2]);
                    mma16(oacc[1][2 * bk],     A1, B[0], B[2]);
                    mma16(oacc[0][2 * bk + 1], A0, B[1], B[3]);
                    mma16(oacc[1][2 * bk + 1], A1, B[1], B[3]);
                }
                if (hasN1) {
                    *(__half2*)&KhN[nk * SQK + ck * 8 + 2 * u] =
                        __floats2half2_rn(kx0, kx1);
                    kx0 = nx0; kx1 = nx1;
                }
            }
        }
    }

    // ---- finalize: row sums -> inv, normalize + store O^T ----
#pragma unroll
    for (int q = 0; q < 4; q++) {
        rsum[q] += __shfl_xor_sync(0xffffffffu, rsum[q], 1);
        rsum[q] += __shfl_xor_sync(0xffffffffu, rsum[q], 2);
    }
    __syncthreads();
    if (tig == 0) {
        float* rs = sm + ORA + wn * 128;
        const int mb = wm * 32;
        rs[mb + g]      = rsum[0];
        rs[mb + g + 8]  = rsum[1];
        rs[mb + g + 16] = rsum[2];
        rs[mb + g + 24] = rsum[3];
    }
    __syncthreads();
    if (t < 128)
        sm[OINV + t] = 1.0f / (sm[ORA + t] + sm[ORA + 128 + t] +
                               sm[ORA + 256 + t] + sm[ORA + 384 + t]);
    __syncthreads();

    {
        const int cb = wc2 * 32, mb2 = wm2 * 64;
#pragma unroll
        for (int i = 0; i < 2; i++)
#pragma unroll
            for (int f = 0; f < 8; f++) {
                int m_ = mb2 + 8 * f + 2 * tig;
                float iv0 = sm[OINV + m_], iv1 = sm[OINV + m_ + 1];
                int cv = cb + 16 * i + g;
                float* o0 = out + ((size_t)b * CVD + cv0 + cv) * MQ + m0 + m_;
                float* o1 = o0 + (size_t)8 * MQ;
                *(float2*)o0 = make_float2(oacc[i][f][0] * iv0, oacc[i][f][1] * iv1);
                *(float2*)o1 = make_float2(oacc[i][f][2] * iv0, oacc[i][f][3] * iv1);
            }
    }
}

// ---------------------------------------------------------------------------
extern "C" void kernel_launch(void* const* d_in, const int* in_sizes, int n_in,
                              void* d_out, int out_size) {
    const float* mk = (const float*)d_in[0];
    const float* qk = (const float*)d_in[1];
    const float* mv = (const float*)d_in[2];
    float* out = (float*)d_out;

    cudaFuncSetAttribute(mr_kernel, cudaFuncAttributeMaxDynamicSharedMemorySize,
                         SMEM_BYTES);
    dim3 grid(MQ / 128, CVD / 256, BATCH);   // 18 x 2 x 4 = 144 CTAs (one wave)
    mr_kernel<<<grid, THREADS, SMEM_BYTES>>>(mk, qk, mv, out);
}